// round 9
// baseline (speedup 1.0000x reference)
#include <cuda_runtime.h>
#include <float.h>

#define BATCH   32
#define HH      2048
#define WW      2048
#define NPB     (HH * WW)              // 4194304 elements per batch
#define CHUNKS  128
#define TPB     256
#define EPC     (NPB / CHUNKS)         // 32768 elements per chunk
#define V4PC    (EPC / 4)              // 8192 float4 per chunk
#define ITERS   (V4PC / TPB)           // 32 float4 per thread
#define K       16
#define RCAP    256                    // per-block candidate region (mean ~7.6 hits)
#define SELCAP  4096                   // smem select capacity == TPB*K (reused by fallback)
#define THRESH  3.5f                   // P(N(0,1)>3.5) ~ 2.33e-4 -> ~975 cands/batch

// ---- device scratch (no allocations allowed) ----
__device__ unsigned long long g_cand[(size_t)BATCH * CHUNKS * RCAP];  // 8 MB
__device__ int                g_bcnt[BATCH * CHUNKS];
__device__ float              g_bloss[BATCH];
__device__ int                g_done;

// Monotonic float -> uint mapping (total order preserved).
__device__ __forceinline__ unsigned int fkey(float f) {
    unsigned int b = __float_as_uint(f);
    return b ^ ((unsigned int)(((int)b) >> 31) | 0x80000000u);
}
// Packed key: value desc primary, index asc secondary (jax top_k tie rule).
// Any finite-value key is >= 2^32 > 0, so 0 is a safe "empty" sentinel.
__device__ __forceinline__ unsigned long long make_key(float v, int idx) {
    return ((unsigned long long)fkey(v) << 32) | (unsigned int)(~idx);
}
__device__ __forceinline__ int key_to_idx(unsigned long long k) {
    return (int)(~(unsigned int)k) & (NPB - 1);
}

// ---------------- kernel 1: streaming threshold scan ----------------
// Mainline per float4: LDG.128 + 3 FMNMX + FSETP. Hits buffered via smem
// atomics, dumped coalesced to this block's private region. Also re-arms the
// last-block ticket for kernel 2 (stream-ordered, once per launch/replay).
__global__ __launch_bounds__(TPB, 8) void topk_scan(const float* __restrict__ in) {
    const int blk   = blockIdx.x;
    const int batch = blk / CHUNKS;
    const int chunk = blk % CHUNKS;
    const int tid   = threadIdx.x;

    if (blk == 0 && tid == 0) g_done = 0;      // re-arm ticket every run

    const float4* __restrict__ p = reinterpret_cast<const float4*>(
        in + (size_t)batch * NPB + (size_t)chunk * EPC);
    const int idx_base0 = chunk * EPC;

    __shared__ unsigned long long sbuf[RCAP];
    __shared__ int scnt;
    if (tid == 0) scnt = 0;
    __syncthreads();

#pragma unroll 16
    for (int it = 0; it < ITERS; ++it) {
        const int v4 = it * TPB + tid;
        float4 q = __ldcs(p + v4);
        float m = fmaxf(fmaxf(q.x, q.y), fmaxf(q.z, q.w));
        if (m > THRESH) {                                    // ~0.09% of groups
            const int base = idx_base0 + (v4 << 2);
            unsigned long long kk[4];
            int n = 0;
            if (q.x > THRESH) kk[n++] = make_key(q.x, base + 0);
            if (q.y > THRESH) kk[n++] = make_key(q.y, base + 1);
            if (q.z > THRESH) kk[n++] = make_key(q.z, base + 2);
            if (q.w > THRESH) kk[n++] = make_key(q.w, base + 3);
            int pos = atomicAdd(&scnt, n);                   // smem atomic
            for (int j = 0; j < n; ++j)
                if (pos + j < RCAP) sbuf[pos + j] = kk[j];
        }
    }
    __syncthreads();

    const int c = scnt;
    unsigned long long* reg = g_cand + (size_t)blk * RCAP;
    for (int i = tid; i < min(c, RCAP); i += TPB) reg[i] = sbuf[i];
    if (tid == 0) g_bcnt[blk] = c;                           // >RCAP marks overflow
}

// ---- exact-fallback helpers (R2-proven merge machinery, on packed keys) ----
__device__ __forceinline__ void ins16k(unsigned long long k, unsigned long long (&tv)[K]) {
#pragma unroll
    for (int j = 0; j < K; ++j) {
        if (k > tv[j]) { unsigned long long f = tv[j]; tv[j] = k; k = f; }
    }
}
__device__ __forceinline__ void merge_lists_k(unsigned long long* sv, int abase, int bbase) {
    unsigned long long rv[K];
    int x = 0, y = 0;
#pragma unroll
    for (int r = 0; r < K; ++r) {
        unsigned long long a = sv[abase + x], b = sv[bbase + y];
        if (a > b) { rv[r] = a; ++x; } else { rv[r] = b; ++y; }
    }
#pragma unroll
    for (int r = 0; r < K; ++r) sv[abase + r] = rv[r];
}

__device__ __forceinline__ float smooth_l1(float pred, float target) {
    float d  = pred - target;
    float ad = fabsf(d);
    return (ad < 1.0f) ? 0.5f * d * d : ad - 0.5f;
}

// ---------------- kernel 2: fixup + select + loss + final reduce (fused) ----------------
__global__ __launch_bounds__(TPB) void select_loss(const float* __restrict__ center_rate,
                                                   const float* __restrict__ in,
                                                   float* __restrict__ out) {
    const int batch = blockIdx.x;
    const int tid   = threadIdx.x;
    const int lane  = tid & 31, wid = tid >> 5;

    __shared__ int cnts[CHUNKS];
    __shared__ int offs[CHUNKS + 1];
    __shared__ unsigned long long sk[SELCAP];   // 32 KB; also fallback merge buffer
    __shared__ unsigned long long red[8];
    __shared__ unsigned long long winner;
    __shared__ int widx[K];
    __shared__ int s_bad;

    if (tid == 0) s_bad = 0;
    if (tid < CHUNKS) {
        int c = g_bcnt[batch * CHUNKS + tid];
        if (c > RCAP) atomicOr(&s_bad, 1);
        cnts[tid] = (c > RCAP) ? RCAP : c;
    }
    __syncthreads();
    if (tid == 0) {
        int acc = 0;
        for (int r = 0; r < CHUNKS; ++r) { offs[r] = acc; acc += cnts[r]; }
        offs[CHUNKS] = acc;
    }
    __syncthreads();
    int total = offs[CHUNKS];

    if (!s_bad && total >= K && total <= SELCAP) {
        // Normal path: compact all regions into smem (each warp takes 16 regions).
        for (int r = wid * (CHUNKS / 8); r < (wid + 1) * (CHUNKS / 8); ++r) {
            const int c = cnts[r];
            const unsigned long long* reg = g_cand + (size_t)(batch * CHUNKS + r) * RCAP;
            for (int i = lane; i < c; i += 32) sk[offs[r] + i] = reg[i];
        }
        __syncthreads();
    } else {
        // Exact fallback (never expected): full batch re-scan, merge tree in sk.
        const float* bp = in + (size_t)batch * NPB;
        unsigned long long tv[K];
#pragma unroll
        for (int j = 0; j < K; ++j) tv[j] = 0ull;
        for (int i = tid; i < NPB; i += TPB) {
            unsigned long long k = make_key(bp[i], i);
            if (k > tv[K - 1]) ins16k(k, tv);
        }
        __syncthreads();                        // sk free for reuse
#pragma unroll
        for (int j = 0; j < K; ++j) sk[tid * K + j] = tv[j];
        for (int s = 1; s < TPB; s <<= 1) {
            __syncthreads();
            if (tid < TPB / (s << 1)) {
                const int abase = (tid * (s << 1)) * K;
                merge_lists_k(sk, abase, abase + s * K);
            }
        }
        __syncthreads();
        total = K;                              // top-16 now in sk[0..15]
        __syncthreads();
    }

    unsigned long long prev = ~0ull;            // strictly-decreasing key knockout
    for (int r = 0; r < K; ++r) {
        unsigned long long best = 0ull;
        for (int j = tid; j < total; j += TPB) {
            unsigned long long k = sk[j];
            if (k < prev && k > best) best = k;
        }
#pragma unroll
        for (int o = 16; o; o >>= 1) {
            unsigned long long ov = __shfl_down_sync(0xffffffffu, best, o);
            if (ov > best) best = ov;
        }
        if (lane == 0) red[wid] = best;
        __syncthreads();
        if (tid == 0) {
            unsigned long long b = red[0];
#pragma unroll
            for (int w = 1; w < 8; ++w) if (red[w] > b) b = red[w];
            winner  = b;
            widx[r] = key_to_idx(b);
        }
        __syncthreads();
        prev = winner;
    }

    if (tid < K) {
        const int id = widx[tid];
        const float p0 = (float)(id / WW) * (1.0f / (float)(HH - 1));
        const float p1 = (float)(id % WW) * (1.0f / (float)(WW - 1));
        const float t0 = center_rate[batch * 2 + 0];
        const float t1 = center_rate[batch * 2 + 1];
        float l = smooth_l1(p0, t0) + smooth_l1(p1, t1);
#pragma unroll
        for (int o = 8; o; o >>= 1) l += __shfl_down_sync(0x0000ffffu, l, o);
        if (tid == 0) g_bloss[batch] = l;
    }
    __syncthreads();

    // Last-block-done final reduce: fixed-order sum -> deterministic output.
    if (tid == 0) {
        __threadfence();
        int ticket = atomicAdd(&g_done, 1);
        if (ticket == BATCH - 1) {
            __threadfence();
            float acc = 0.0f;
            for (int b = 0; b < BATCH; ++b)
                acc += *((volatile float*)&g_bloss[b]);
            out[0] = acc * (1.0f / (float)(BATCH * K * 2));
        }
    }
}

extern "C" void kernel_launch(void* const* d_in, const int* in_sizes, int n_in,
                              void* d_out, int out_size) {
    // cls_input = 33554432 elems; center_rate = 64.
    const float* cls = (const float*)d_in[0];
    const float* cr  = (const float*)d_in[1];
    if (n_in >= 2 && in_sizes[0] < in_sizes[1]) {   // defensive order check
        cls = (const float*)d_in[1];
        cr  = (const float*)d_in[0];
    }
    float* out = (float*)d_out;

    topk_scan<<<BATCH * CHUNKS, TPB>>>(cls);
    select_loss<<<BATCH, TPB>>>(cr, cls, out);
}

// round 11
// speedup vs baseline: 1.0167x; 1.0167x over previous
#include <cuda_runtime.h>
#include <float.h>

#define BATCH   32
#define HH      2048
#define WW      2048
#define NPB     (HH * WW)              // 4194304 elements per batch
#define CHUNKS  128
#define TPB     256
#define EPC     (NPB / CHUNKS)         // 32768 elements per chunk
#define V4PC    (EPC / 4)              // 8192 float4 per chunk
#define ITERS   (V4PC / TPB)           // 32 float4 per thread
#define K       16
#define RCAP    256                    // per-block candidate region (mean ~7.6 hits)
#define SELCAP  4096                   // smem key buffer == TPB*K (merge tree reuses it)
#define THRESH  3.5f                   // P(N(0,1)>3.5) ~ 2.33e-4 -> ~975 cands/batch

// ---- device scratch (no allocations allowed) ----
__device__ unsigned long long g_cand[(size_t)BATCH * CHUNKS * RCAP];  // 8 MB
__device__ int                g_bcnt[BATCH * CHUNKS];
__device__ float              g_bloss[BATCH];
__device__ int                g_done;

// Monotonic float -> uint mapping (total order preserved).
__device__ __forceinline__ unsigned int fkey(float f) {
    unsigned int b = __float_as_uint(f);
    return b ^ ((unsigned int)(((int)b) >> 31) | 0x80000000u);
}
// Packed key: value desc primary, index asc secondary (jax top_k tie rule).
// Any finite-value key is >= 2^32 > 0, so 0 is a safe "empty" sentinel.
__device__ __forceinline__ unsigned long long make_key(float v, int idx) {
    return ((unsigned long long)fkey(v) << 32) | (unsigned int)(~idx);
}
__device__ __forceinline__ int key_to_idx(unsigned long long k) {
    return (int)(~(unsigned int)k) & (NPB - 1);
}

// ---------------- kernel 1: streaming threshold scan (unchanged, passing since R7) ----------------
__global__ __launch_bounds__(TPB, 8) void topk_scan(const float* __restrict__ in) {
    const int blk   = blockIdx.x;
    const int batch = blk / CHUNKS;
    const int chunk = blk % CHUNKS;
    const int tid   = threadIdx.x;

    if (blk == 0 && tid == 0) g_done = 0;      // re-arm ticket every run

    const float4* __restrict__ p = reinterpret_cast<const float4*>(
        in + (size_t)batch * NPB + (size_t)chunk * EPC);
    const int idx_base0 = chunk * EPC;

    __shared__ unsigned long long sbuf[RCAP];
    __shared__ int scnt;
    if (tid == 0) scnt = 0;
    __syncthreads();

#pragma unroll 16
    for (int it = 0; it < ITERS; ++it) {
        const int v4 = it * TPB + tid;
        float4 q = __ldcs(p + v4);
        float m = fmaxf(fmaxf(q.x, q.y), fmaxf(q.z, q.w));
        if (m > THRESH) {                                    // ~0.09% of groups
            const int base = idx_base0 + (v4 << 2);
            unsigned long long kk[4];
            int n = 0;
            if (q.x > THRESH) kk[n++] = make_key(q.x, base + 0);
            if (q.y > THRESH) kk[n++] = make_key(q.y, base + 1);
            if (q.z > THRESH) kk[n++] = make_key(q.z, base + 2);
            if (q.w > THRESH) kk[n++] = make_key(q.w, base + 3);
            int pos = atomicAdd(&scnt, n);                   // smem atomic
            for (int j = 0; j < n; ++j)
                if (pos + j < RCAP) sbuf[pos + j] = kk[j];
        }
    }
    __syncthreads();

    const int c = scnt;
    unsigned long long* reg = g_cand + (size_t)blk * RCAP;
    for (int i = tid; i < min(c, RCAP); i += TPB) reg[i] = sbuf[i];
    if (tid == 0) g_bcnt[blk] = c;                           // >RCAP marks overflow
}

// ---- merge machinery (R2-proven) on packed keys ----
__device__ __forceinline__ void ins16k(unsigned long long k, unsigned long long (&tv)[K]) {
#pragma unroll
    for (int j = 0; j < K; ++j) {
        if (k > tv[j]) { unsigned long long f = tv[j]; tv[j] = k; k = f; }
    }
}
__device__ __forceinline__ void merge_lists_k(unsigned long long* sv, int abase, int bbase) {
    unsigned long long rv[K];
    int x = 0, y = 0;
#pragma unroll
    for (int r = 0; r < K; ++r) {
        unsigned long long a = sv[abase + x], b = sv[bbase + y];
        if (a > b) { rv[r] = a; ++x; } else { rv[r] = b; ++y; }
    }
#pragma unroll
    for (int r = 0; r < K; ++r) sv[abase + r] = rv[r];
}

__device__ __forceinline__ float smooth_l1(float pred, float target) {
    float d  = pred - target;
    float ad = fabsf(d);
    return (ad < 1.0f) ? 0.5f * d * d : ad - 0.5f;
}

// ---------------- kernel 2: select + loss + final reduce (merge-tree version) ----------------
__global__ __launch_bounds__(TPB) void select_loss(const float* __restrict__ center_rate,
                                                   const float* __restrict__ in,
                                                   float* __restrict__ out) {
    const int batch = blockIdx.x;
    const int tid   = threadIdx.x;
    const int lane  = tid & 31, wid = tid >> 5;

    __shared__ int cnts[CHUNKS];
    __shared__ int offs[CHUNKS];
    __shared__ int wsum[4];
    __shared__ unsigned long long sk[SELCAP];   // 32 KB: compacted keys, then merge lists
    __shared__ int s_bad, s_total;
    __shared__ int s_last;

    if (tid == 0) { s_bad = 0; }
    __syncthreads();
    if (tid < CHUNKS) {
        int c = g_bcnt[batch * CHUNKS + tid];
        if (c > RCAP) atomicOr(&s_bad, 1);
        cnts[tid] = (c > RCAP) ? RCAP : c;
    }
    __syncthreads();

    // Parallel exclusive prefix over 128 counts: 4 warp shfl-scans + combine.
    if (tid < CHUNKS) {
        int v = cnts[tid];
        int inc = v;
#pragma unroll
        for (int o = 1; o < 32; o <<= 1) {
            int t = __shfl_up_sync(0xffffffffu, inc, o);
            if (lane >= o) inc += t;
        }
        if (lane == 31) wsum[wid] = inc;
        offs[tid] = inc - v;                    // exclusive within warp
    }
    __syncthreads();
    if (tid == 0) {
        // R9 BUG FIX: wsum[3] must be warp-3's exclusive OFFSET (a2), with the
        // grand total kept separately. R9 set wsum[3]=a2+W3, displacing chunks
        // 96-127 outside the gathered range and reading uninitialized smem.
        int a0 = wsum[0], a1 = a0 + wsum[1], a2 = a1 + wsum[2];
        int w3 = wsum[3];
        wsum[0] = 0; wsum[1] = a0; wsum[2] = a1; wsum[3] = a2;
        s_total = a2 + w3;
    }
    __syncthreads();
    if (tid < CHUNKS) offs[tid] += wsum[wid];
    __syncthreads();
    const int total = s_total;

    // Per-thread sorted top-16 lists (registers), from compacted keys or fallback.
    unsigned long long tv[K];
#pragma unroll
    for (int j = 0; j < K; ++j) tv[j] = 0ull;

    if (!s_bad && total >= K && total <= SELCAP) {
        // Compact: each warp takes every-8th region.
        for (int r = wid; r < CHUNKS; r += 8) {
            const int c = cnts[r];
            const unsigned long long* reg = g_cand + (size_t)(batch * CHUNKS + r) * RCAP;
            for (int i = lane; i < c; i += 32) sk[offs[r] + i] = reg[i];
        }
        __syncthreads();
        for (int j = tid; j < total; j += TPB) {    // ~4 keys/thread
            unsigned long long k = sk[j];
            if (k > tv[K - 1]) ins16k(k, tv);
        }
    } else {
        // Exact fallback (never expected): full batch re-scan.
        const float* bp = in + (size_t)batch * NPB;
        for (int i = tid; i < NPB; i += TPB) {
            unsigned long long k = make_key(bp[i], i);
            if (k > tv[K - 1]) ins16k(k, tv);
        }
    }
    __syncthreads();                            // sk free for reuse

    // 256 sorted 16-lists -> merge tree (8 levels) -> sk[0..15] = batch top-16.
#pragma unroll
    for (int j = 0; j < K; ++j) sk[tid * K + j] = tv[j];
    for (int s = 1; s < TPB; s <<= 1) {
        __syncthreads();
        if (tid < TPB / (s << 1)) {
            const int abase = (tid * (s << 1)) * K;
            merge_lists_k(sk, abase, abase + s * K);
        }
    }
    __syncthreads();

    if (tid < K) {
        const int id = key_to_idx(sk[tid]);
        const float p0 = (float)(id / WW) * (1.0f / (float)(HH - 1));
        const float p1 = (float)(id % WW) * (1.0f / (float)(WW - 1));
        const float t0 = center_rate[batch * 2 + 0];
        const float t1 = center_rate[batch * 2 + 1];
        float l = smooth_l1(p0, t0) + smooth_l1(p1, t1);
#pragma unroll
        for (int o = 8; o; o >>= 1) l += __shfl_down_sync(0x0000ffffu, l, o);
        if (tid == 0) g_bloss[batch] = l;
    }
    __syncthreads();

    // Last-block-done final reduce (warp-parallel, fixed shuffle order -> deterministic).
    if (tid == 0) {
        __threadfence();
        int ticket = atomicAdd(&g_done, 1);
        s_last = (ticket == BATCH - 1);
        if (s_last) __threadfence();
    }
    __syncthreads();
    if (s_last && tid < 32) {
        float l = *((volatile float*)&g_bloss[tid]);
#pragma unroll
        for (int o = 16; o; o >>= 1) l += __shfl_down_sync(0xffffffffu, l, o);
        if (tid == 0) out[0] = l * (1.0f / (float)(BATCH * K * 2));
    }
}

extern "C" void kernel_launch(void* const* d_in, const int* in_sizes, int n_in,
                              void* d_out, int out_size) {
    // cls_input = 33554432 elems; center_rate = 64.
    const float* cls = (const float*)d_in[0];
    const float* cr  = (const float*)d_in[1];
    if (n_in >= 2 && in_sizes[0] < in_sizes[1]) {   // defensive order check
        cls = (const float*)d_in[1];
        cr  = (const float*)d_in[0];
    }
    float* out = (float*)d_out;

    topk_scan<<<BATCH * CHUNKS, TPB>>>(cls);
    select_loss<<<BATCH, TPB>>>(cr, cls, out);
}

// round 12
// speedup vs baseline: 1.0548x; 1.0375x over previous
#include <cuda_runtime.h>
#include <float.h>

#define BATCH   32
#define HH      2048
#define WW      2048
#define NPB     (HH * WW)              // 4194304 elements per batch
#define CHUNKS  32
#define TPB     256
#define EPC     (NPB / CHUNKS)         // 131072 elements per chunk
#define V4PC    (EPC / 4)              // 32768 float4 per chunk
#define ITERS   (V4PC / TPB)           // 128 float4 per thread
#define K       16
#define RCAP    256                    // per-block region (mean ~30 hits, >30 sigma margin)
#define SELCAP  4096                   // smem key buffer == TPB*K (merge tree reuses it)
#define THRESH  3.5f                   // P(N(0,1)>3.5) ~ 2.33e-4 -> ~975 cands/batch

// ---- device scratch (no allocations allowed) ----
__device__ unsigned long long g_cand[(size_t)BATCH * CHUNKS * RCAP];  // 2 MB
__device__ int                g_bcnt[BATCH * CHUNKS];
__device__ float              g_bloss[BATCH];

// Monotonic float -> uint mapping (total order preserved).
__device__ __forceinline__ unsigned int fkey(float f) {
    unsigned int b = __float_as_uint(f);
    return b ^ ((unsigned int)(((int)b) >> 31) | 0x80000000u);
}
// Packed key: value desc primary, index asc secondary (jax top_k tie rule).
// Any finite-value key is >= 2^32 > 0, so 0 is a safe "empty" sentinel.
__device__ __forceinline__ unsigned long long make_key(float v, int idx) {
    return ((unsigned long long)fkey(v) << 32) | (unsigned int)(~idx);
}
__device__ __forceinline__ int key_to_idx(unsigned long long k) {
    return (int)(~(unsigned int)k) & (NPB - 1);
}

// ---------------- kernel 1: streaming threshold scan (single wave: 1024 blocks) ----------------
__global__ __launch_bounds__(TPB, 8) void topk_scan(const float* __restrict__ in) {
    const int blk   = blockIdx.x;
    const int batch = blk / CHUNKS;
    const int chunk = blk % CHUNKS;
    const int tid   = threadIdx.x;

    const float4* __restrict__ p = reinterpret_cast<const float4*>(
        in + (size_t)batch * NPB + (size_t)chunk * EPC);
    const int idx_base0 = chunk * EPC;

    __shared__ unsigned long long sbuf[RCAP];
    __shared__ int scnt;
    if (tid == 0) scnt = 0;
    __syncthreads();

#pragma unroll 16
    for (int it = 0; it < ITERS; ++it) {
        const int v4 = it * TPB + tid;
        float4 q = __ldcs(p + v4);
        float m = fmaxf(fmaxf(q.x, q.y), fmaxf(q.z, q.w));
        if (m > THRESH) {                                    // ~0.09% of groups
            const int base = idx_base0 + (v4 << 2);
            unsigned long long kk[4];
            int n = 0;
            if (q.x > THRESH) kk[n++] = make_key(q.x, base + 0);
            if (q.y > THRESH) kk[n++] = make_key(q.y, base + 1);
            if (q.z > THRESH) kk[n++] = make_key(q.z, base + 2);
            if (q.w > THRESH) kk[n++] = make_key(q.w, base + 3);
            int pos = atomicAdd(&scnt, n);                   // smem atomic
            for (int j = 0; j < n; ++j)
                if (pos + j < RCAP) sbuf[pos + j] = kk[j];
        }
    }
    __syncthreads();

    const int c = scnt;
    unsigned long long* reg = g_cand + (size_t)blk * RCAP;
    for (int i = tid; i < min(c, RCAP); i += TPB) reg[i] = sbuf[i];
    if (tid == 0) g_bcnt[blk] = c;                           // >RCAP marks overflow
}

// ---- merge machinery (R2-proven) on packed keys ----
__device__ __forceinline__ void ins16k(unsigned long long k, unsigned long long (&tv)[K]) {
#pragma unroll
    for (int j = 0; j < K; ++j) {
        if (k > tv[j]) { unsigned long long f = tv[j]; tv[j] = k; k = f; }
    }
}
__device__ __forceinline__ void merge_lists_k(unsigned long long* sv, int abase, int bbase) {
    unsigned long long rv[K];
    int x = 0, y = 0;
#pragma unroll
    for (int r = 0; r < K; ++r) {
        unsigned long long a = sv[abase + x], b = sv[bbase + y];
        if (a > b) { rv[r] = a; ++x; } else { rv[r] = b; ++y; }
    }
#pragma unroll
    for (int r = 0; r < K; ++r) sv[abase + r] = rv[r];
}

__device__ __forceinline__ float smooth_l1(float pred, float target) {
    float d  = pred - target;
    float ad = fabsf(d);
    return (ad < 1.0f) ? 0.5f * d * d : ad - 0.5f;
}

// ---------------- kernel 2: fixup-check + compact + merge tree + loss ----------------
__global__ __launch_bounds__(TPB) void select_loss(const float* __restrict__ center_rate,
                                                   const float* __restrict__ in) {
    const int batch = blockIdx.x;
    const int tid   = threadIdx.x;
    const int lane  = tid & 31, wid = tid >> 5;

    __shared__ int cnts[CHUNKS];
    __shared__ int offs[CHUNKS];
    __shared__ unsigned long long sk[SELCAP];   // 32 KB: compacted keys, then merge lists
    __shared__ int s_bad, s_total;

    // Single-warp read + exclusive shfl scan over 32 counts (no cross-warp combine).
    if (tid < 32) {
        int c = g_bcnt[batch * CHUNKS + tid];
        int bad = (c > RCAP) ? 1 : 0;
#pragma unroll
        for (int o = 16; o; o >>= 1) bad |= __shfl_xor_sync(0xffffffffu, bad, o);
        int v = (c > RCAP) ? RCAP : c;
        int inc = v;
#pragma unroll
        for (int o = 1; o < 32; o <<= 1) {
            int t = __shfl_up_sync(0xffffffffu, inc, o);
            if (lane >= o) inc += t;
        }
        cnts[tid] = v;
        offs[tid] = inc - v;                    // exclusive prefix
        if (tid == 31) { s_total = inc; s_bad = bad; }
    }
    __syncthreads();
    const int total = s_total;

    // Per-thread sorted top-16 lists (registers), from compacted keys or fallback.
    unsigned long long tv[K];
#pragma unroll
    for (int j = 0; j < K; ++j) tv[j] = 0ull;

    if (!s_bad && total >= K && total <= SELCAP) {
        // Compact: warp w takes regions w and w+8 ... (4 each).
        for (int r = wid; r < CHUNKS; r += 8) {
            const int c = cnts[r];
            const unsigned long long* reg = g_cand + (size_t)(batch * CHUNKS + r) * RCAP;
            for (int i = lane; i < c; i += 32) sk[offs[r] + i] = reg[i];
        }
        __syncthreads();
        for (int j = tid; j < total; j += TPB) {    // ~4 keys/thread
            unsigned long long k = sk[j];
            if (k > tv[K - 1]) ins16k(k, tv);
        }
    } else {
        // Exact fallback (never expected): full batch re-scan.
        const float* bp = in + (size_t)batch * NPB;
        for (int i = tid; i < NPB; i += TPB) {
            unsigned long long k = make_key(bp[i], i);
            if (k > tv[K - 1]) ins16k(k, tv);
        }
    }
    __syncthreads();                            // sk free for reuse

    // 256 sorted 16-lists -> merge tree (8 levels) -> sk[0..15] = batch top-16.
#pragma unroll
    for (int j = 0; j < K; ++j) sk[tid * K + j] = tv[j];
    for (int s = 1; s < TPB; s <<= 1) {
        __syncthreads();
        if (tid < TPB / (s << 1)) {
            const int abase = (tid * (s << 1)) * K;
            merge_lists_k(sk, abase, abase + s * K);
        }
    }
    __syncthreads();

    if (tid < K) {
        const int id = key_to_idx(sk[tid]);
        const float p0 = (float)(id / WW) * (1.0f / (float)(HH - 1));
        const float p1 = (float)(id % WW) * (1.0f / (float)(WW - 1));
        const float t0 = center_rate[batch * 2 + 0];
        const float t1 = center_rate[batch * 2 + 1];
        float l = smooth_l1(p0, t0) + smooth_l1(p1, t1);
#pragma unroll
        for (int o = 8; o; o >>= 1) l += __shfl_down_sync(0x0000ffffu, l, o);
        if (tid == 0) g_bloss[batch] = l;
    }
}

// ---------------- kernel 3: final scalar ----------------
__global__ void finalize(float* __restrict__ out) {
    float l = (threadIdx.x < BATCH) ? g_bloss[threadIdx.x] : 0.0f;
#pragma unroll
    for (int o = 16; o; o >>= 1) l += __shfl_down_sync(0xffffffffu, l, o);
    if (threadIdx.x == 0) out[0] = l * (1.0f / (float)(BATCH * K * 2));
}

extern "C" void kernel_launch(void* const* d_in, const int* in_sizes, int n_in,
                              void* d_out, int out_size) {
    const float* cls = (const float*)d_in[0];
    const float* cr  = (const float*)d_in[1];
    if (n_in >= 2 && in_sizes[0] < in_sizes[1]) {   // defensive order check
        cls = (const float*)d_in[1];
        cr  = (const float*)d_in[0];
    }
    float* out = (float*)d_out;

    topk_scan<<<BATCH * CHUNKS, TPB>>>(cls);        // 1024 blocks: single wave
    select_loss<<<BATCH, TPB>>>(cr, cls);
    finalize<<<1, 32>>>(out);
}

// round 14
// speedup vs baseline: 1.1465x; 1.0869x over previous
#include <cuda_runtime.h>
#include <float.h>

#define BATCH   32
#define HH      2048
#define WW      2048
#define NPB     (HH * WW)              // 4194304 elements per batch
#define CHUNKS  32
#define TPB     256
#define EPC     (NPB / CHUNKS)         // 131072 elements per chunk
#define V4PC    (EPC / 4)              // 32768 float4 per chunk
#define ITERS   (V4PC / TPB)           // 128 float4 per thread
#define K       16
#define RCAP    256                    // per-block region (mean ~30 hits)
#define SELCAP  4096                   // smem key buffer == TPB*K (merge tree reuses it)
#define THRESH  3.5f                   // P(N(0,1)>3.5) ~ 2.33e-4 -> ~975 cands/batch

// ---- device scratch (no allocations allowed) ----
__device__ unsigned long long g_cand[(size_t)BATCH * CHUNKS * RCAP];  // 2 MB
__device__ int                g_bcnt[BATCH * CHUNKS];
__device__ float              g_bloss[BATCH];
__device__ int                g_done;

// Monotonic float -> uint mapping (total order preserved).
__device__ __forceinline__ unsigned int fkey(float f) {
    unsigned int b = __float_as_uint(f);
    return b ^ ((unsigned int)(((int)b) >> 31) | 0x80000000u);
}
// Packed key: value desc primary, index asc secondary (jax top_k tie rule).
// Any finite-value key is >= 2^32 > 0, so 0 is a safe "empty" sentinel.
__device__ __forceinline__ unsigned long long make_key(float v, int idx) {
    return ((unsigned long long)fkey(v) << 32) | (unsigned int)(~idx);
}
__device__ __forceinline__ int key_to_idx(unsigned long long k) {
    return (int)(~(unsigned int)k) & (NPB - 1);
}

__device__ __forceinline__ void push_hits(float4 q, int base,
                                          unsigned long long* sbuf, int* scnt) {
    unsigned long long kk[4];
    int n = 0;
    if (q.x > THRESH) kk[n++] = make_key(q.x, base + 0);
    if (q.y > THRESH) kk[n++] = make_key(q.y, base + 1);
    if (q.z > THRESH) kk[n++] = make_key(q.z, base + 2);
    if (q.w > THRESH) kk[n++] = make_key(q.w, base + 3);
    int pos = atomicAdd(scnt, n);                            // smem atomic
    for (int j = 0; j < n; ++j)
        if (pos + j < RCAP) sbuf[pos + j] = kk[j];
}

// ---------------- kernel 1: streaming threshold scan (single wave, paired loads) ----------------
__global__ __launch_bounds__(TPB, 8) void topk_scan(const float* __restrict__ in) {
    const int blk   = blockIdx.x;
    const int batch = blk / CHUNKS;
    const int chunk = blk % CHUNKS;
    const int tid   = threadIdx.x;

    if (blk == 0 && tid == 0) g_done = 0;      // re-arm ticket every run

    const float4* __restrict__ p = reinterpret_cast<const float4*>(
        in + (size_t)batch * NPB + (size_t)chunk * EPC);
    const int idx_base0 = chunk * EPC;

    __shared__ unsigned long long sbuf[RCAP];
    __shared__ int scnt;
    if (tid == 0) scnt = 0;
    __syncthreads();

#pragma unroll 8
    for (int it = 0; it < ITERS; it += 2) {
        const int va = it * TPB + tid;
        const int vb = va + TPB;
        float4 qa = __ldcs(p + va);            // two independent loads issued
        float4 qb = __ldcs(p + vb);            // before any consumption (MLP>=2)
        float ma = fmaxf(fmaxf(qa.x, qa.y), fmaxf(qa.z, qa.w));
        float mb = fmaxf(fmaxf(qb.x, qb.y), fmaxf(qb.z, qb.w));
        if (ma > THRESH) push_hits(qa, idx_base0 + (va << 2), sbuf, &scnt);
        if (mb > THRESH) push_hits(qb, idx_base0 + (vb << 2), sbuf, &scnt);
    }
    __syncthreads();

    const int c = scnt;
    unsigned long long* reg = g_cand + (size_t)blk * RCAP;
    for (int i = tid; i < min(c, RCAP); i += TPB) reg[i] = sbuf[i];
    if (tid == 0) g_bcnt[blk] = c;                           // >RCAP marks overflow
}

// ---- merge machinery (R2-proven) on packed keys ----
__device__ __forceinline__ void ins16k(unsigned long long k, unsigned long long (&tv)[K]) {
#pragma unroll
    for (int j = 0; j < K; ++j) {
        if (k > tv[j]) { unsigned long long f = tv[j]; tv[j] = k; k = f; }
    }
}
__device__ __forceinline__ void merge_lists_k(unsigned long long* sv, int abase, int bbase) {
    unsigned long long rv[K];
    int x = 0, y = 0;
#pragma unroll
    for (int r = 0; r < K; ++r) {
        unsigned long long a = sv[abase + x], b = sv[bbase + y];
        if (a > b) { rv[r] = a; ++x; } else { rv[r] = b; ++y; }
    }
#pragma unroll
    for (int r = 0; r < K; ++r) sv[abase + r] = rv[r];
}

__device__ __forceinline__ float smooth_l1(float pred, float target) {
    float d  = pred - target;
    float ad = fabsf(d);
    return (ad < 1.0f) ? 0.5f * d * d : ad - 0.5f;
}

// ---------------- kernel 2: select + loss + ticket-fused final reduce ----------------
__global__ __launch_bounds__(TPB) void select_loss(const float* __restrict__ center_rate,
                                                   const float* __restrict__ in,
                                                   float* __restrict__ out) {
    const int batch = blockIdx.x;
    const int tid   = threadIdx.x;
    const int lane  = tid & 31, wid = tid >> 5;

    __shared__ int cnts[CHUNKS];
    __shared__ int offs[CHUNKS];
    __shared__ unsigned long long sk[SELCAP];   // 32 KB: compacted keys, then merge lists
    __shared__ int s_bad, s_total, s_last;

    // Single-warp read + exclusive shfl scan over 32 counts.
    if (tid < 32) {
        int c = g_bcnt[batch * CHUNKS + tid];
        int bad = (c > RCAP) ? 1 : 0;
#pragma unroll
        for (int o = 16; o; o >>= 1) bad |= __shfl_xor_sync(0xffffffffu, bad, o);
        int v = (c > RCAP) ? RCAP : c;
        int inc = v;
#pragma unroll
        for (int o = 1; o < 32; o <<= 1) {
            int t = __shfl_up_sync(0xffffffffu, inc, o);
            if (lane >= o) inc += t;
        }
        cnts[tid] = v;
        offs[tid] = inc - v;                    // exclusive prefix
        if (tid == 31) { s_total = inc; s_bad = bad; }
    }
    __syncthreads();
    const int total = s_total;

    // Per-thread sorted top-16 lists (registers), from compacted keys or fallback.
    unsigned long long tv[K];
#pragma unroll
    for (int j = 0; j < K; ++j) tv[j] = 0ull;

    if (!s_bad && total >= K && total <= SELCAP) {
        // Compact: warp w takes regions w, w+8, w+16, w+24.
        for (int r = wid; r < CHUNKS; r += 8) {
            const int c = cnts[r];
            const unsigned long long* reg = g_cand + (size_t)(batch * CHUNKS + r) * RCAP;
            for (int i = lane; i < c; i += 32) sk[offs[r] + i] = reg[i];
        }
        __syncthreads();
        for (int j = tid; j < total; j += TPB) {    // ~4 keys/thread
            unsigned long long k = sk[j];
            if (k > tv[K - 1]) ins16k(k, tv);
        }
    } else {
        // Exact fallback (never expected): full batch re-scan.
        const float* bp = in + (size_t)batch * NPB;
        for (int i = tid; i < NPB; i += TPB) {
            unsigned long long k = make_key(bp[i], i);
            if (k > tv[K - 1]) ins16k(k, tv);
        }
    }
    __syncthreads();                            // sk free for reuse

    // 256 sorted 16-lists -> merge tree (8 levels) -> sk[0..15] = batch top-16.
#pragma unroll
    for (int j = 0; j < K; ++j) sk[tid * K + j] = tv[j];
    for (int s = 1; s < TPB; s <<= 1) {
        __syncthreads();
        if (tid < TPB / (s << 1)) {
            const int abase = (tid * (s << 1)) * K;
            merge_lists_k(sk, abase, abase + s * K);
        }
    }
    __syncthreads();

    if (tid < K) {
        const int id = key_to_idx(sk[tid]);
        const float p0 = (float)(id / WW) * (1.0f / (float)(HH - 1));
        const float p1 = (float)(id % WW) * (1.0f / (float)(WW - 1));
        const float t0 = center_rate[batch * 2 + 0];
        const float t1 = center_rate[batch * 2 + 1];
        float l = smooth_l1(p0, t0) + smooth_l1(p1, t1);
#pragma unroll
        for (int o = 8; o; o >>= 1) l += __shfl_down_sync(0x0000ffffu, l, o);
        if (tid == 0) g_bloss[batch] = l;
    }
    __syncthreads();

    // Last-block-done final reduce (fixed shuffle order -> deterministic).
    if (tid == 0) {
        __threadfence();
        int ticket = atomicAdd(&g_done, 1);
        s_last = (ticket == BATCH - 1);
        if (s_last) __threadfence();
    }
    __syncthreads();
    if (s_last && tid < 32) {
        float l = *((volatile float*)&g_bloss[tid]);
#pragma unroll
        for (int o = 16; o; o >>= 1) l += __shfl_down_sync(0xffffffffu, l, o);
        if (tid == 0) out[0] = l * (1.0f / (float)(BATCH * K * 2));
    }
}

extern "C" void kernel_launch(void* const* d_in, const int* in_sizes, int n_in,
                              void* d_out, int out_size) {
    const float* cls = (const float*)d_in[0];
    const float* cr  = (const float*)d_in[1];
    if (n_in >= 2 && in_sizes[0] < in_sizes[1]) {   // defensive order check
        cls = (const float*)d_in[1];
        cr  = (const float*)d_in[0];
    }
    float* out = (float*)d_out;

    topk_scan<<<BATCH * CHUNKS, TPB>>>(cls);        // 1024 blocks: single wave
    select_loss<<<BATCH, TPB>>>(cr, cls, out);
}